// round 7
// baseline (speedup 1.0000x reference)
#include <cuda_runtime.h>

#define NN 50000
#define NE 800000
#define ET (NN + NE)          // 850000 edges incl self-loops
#define NEGS 0.2f

// ---------------- static scratch (no allocation allowed) ----------------
__device__ float g_h [NN * 256];      // layer input/output rows (stride = HC of layer)
__device__ float g_xs[NN * 256];      // xs = h @ W
__device__ float g_as[NN * 8];        // per-node alpha_src
__device__ float g_ad[NN * 8];        // per-node alpha_dst
__device__ int   g_deg[NN];
__device__ int   g_off[NN + 1];
__device__ int   g_cur[NN];
__device__ int   g_srcs[ET];
__device__ int   g_eids[ET];
__device__ float g_Me[3 * 8];
__device__ float g_aeself[8];
__device__ float g_eacc[3];
__device__ int   g_idx64;             // 1 if indices are int64, 0 if int32

// index load helper: branch on runtime dtype flag, clamp to [0, NN)
__device__ __forceinline__ int ld_idx(const void* p, long long i, int is64) {
    int v;
    if (is64) v = (int)((const long long*)p)[i];
    else      v = ((const int*)p)[i];
    v = v < 0 ? 0 : (v >= NN ? NN - 1 : v);
    return v;
}

// ---------------- dtype detect: odd 32-bit words all zero => int64 ----------------
__global__ void k_detect(const int* __restrict__ ei_raw) {
    // single thread; inspects 64 candidate high-words
    int allzero = 1;
    for (int i = 0; i < 64; i++)
        if (ei_raw[2 * i + 1] != 0) { allzero = 0; break; }
    g_idx64 = allzero;
}

// ---------------- init: deg=1 (self loop), zero mean accum ----------------
__global__ void k_init() {
    int t = blockIdx.x * blockDim.x + threadIdx.x;
    if (t < NN) g_deg[t] = 1;
    if (t < 3) g_eacc[t] = 0.f;
}

// ---------------- histogram of dst + edge_attr mean accumulation ----------------
__global__ void k_edge_pre(const void* __restrict__ ei, const float* __restrict__ ea) {
    int t = blockIdx.x * blockDim.x + threadIdx.x;
    int is64 = g_idx64;
    float a0 = 0.f, a1 = 0.f, a2 = 0.f;
    if (t < NE) {
        atomicAdd(&g_deg[ld_idx(ei, (long long)NE + t, is64)], 1);
        a0 = ea[3 * t]; a1 = ea[3 * t + 1]; a2 = ea[3 * t + 2];
    }
#pragma unroll
    for (int o = 16; o; o >>= 1) {
        a0 += __shfl_down_sync(0xffffffffu, a0, o);
        a1 += __shfl_down_sync(0xffffffffu, a1, o);
        a2 += __shfl_down_sync(0xffffffffu, a2, o);
    }
    __shared__ float s[3][8];
    int w = threadIdx.x >> 5;
    if ((threadIdx.x & 31) == 0) { s[0][w] = a0; s[1][w] = a1; s[2][w] = a2; }
    __syncthreads();
    if (threadIdx.x == 0) {
        float t0 = 0.f, t1 = 0.f, t2 = 0.f;
        for (int i = 0; i < 8; i++) { t0 += s[0][i]; t1 += s[1][i]; t2 += s[2][i]; }
        atomicAdd(&g_eacc[0], t0); atomicAdd(&g_eacc[1], t1); atomicAdd(&g_eacc[2], t2);
    }
}

// ---------------- exclusive scan of degrees (single block) ----------------
__global__ void k_scan() {
    __shared__ int s[1024];
    int t = threadIdx.x;
    const int per = (NN + 1023) / 1024;
    int b = t * per;
    int e = b + per; if (e > NN) e = NN;
    int sum = 0;
    for (int i = b; i < e; i++) sum += g_deg[i];
    s[t] = sum;
    __syncthreads();
    for (int off = 1; off < 1024; off <<= 1) {
        int v = (t >= off) ? s[t - off] : 0;
        __syncthreads();
        s[t] += v;
        __syncthreads();
    }
    int run = (t > 0) ? s[t - 1] : 0;
    for (int i = b; i < e; i++) {
        g_off[i] = run; g_cur[i] = run;
        run += g_deg[i];
    }
    if (t == 0) g_off[NN] = s[1023];
}

// ---------------- scatter edges into CSR ----------------
__global__ void k_scatter(const void* __restrict__ ei) {
    int t = blockIdx.x * blockDim.x + threadIdx.x;
    if (t >= ET) return;
    int is64 = g_idx64;
    int src, dst;
    if (t < NE) { src = ld_idx(ei, t, is64); dst = ld_idx(ei, (long long)NE + t, is64); }
    else        { src = dst = t - NE; }
    int p = atomicAdd(&g_cur[dst], 1);
    if (p < ET) { g_srcs[p] = src; g_eids[p] = t; }
}

// ---------------- embedding lookup -> g_h ----------------
__global__ void k_embed(const void* __restrict__ x, const float* __restrict__ emb) {
    int t = blockIdx.x * blockDim.x + threadIdx.x;
    if (t >= NN * 128) return;
    int is64 = g_idx64;
    int n = t >> 7, d = t & 127;
    int v;
    if (is64) v = (int)((const long long*)x)[n];
    else      v = ((const int*)x)[n];
    v = v < 0 ? 0 : (v > 8 ? 8 : v);   // VOCAB=9
    g_h[n * 128 + d] = emb[v * 128 + d];
}

// ---------------- per-layer prep: Me[d][h] = sum_o We[d][h*32+o]*ae[h][o]; aeself ----------------
__global__ void k_prep(const float* __restrict__ We, const float* __restrict__ ae, int heads) {
    int t = threadIdx.x;
    if (t < 3 * heads) {
        int d = t / heads, h = t % heads;
        float s = 0.f;
        for (int o = 0; o < 32; o++) s += We[d * heads * 32 + h * 32 + o] * ae[h * 32 + o];
        g_Me[d * heads + h] = s;
    }
    __syncthreads();
    if (t < heads) {
        float s = 0.f;
        for (int d = 0; d < 3; d++) s += (g_eacc[d] * (1.f / NE)) * g_Me[d * heads + t];
        g_aeself[t] = s;
    }
}

// ---------------- tiled fp32 GEMM: g_xs[M,N] = g_h[M,K] @ B[K,N] ----------------
// 128x128 tile, BK=8, 256 threads, 8x8 microtile
__global__ void k_gemm(const float* __restrict__ B, int M, int K, int N) {
    __shared__ float As[8][128];
    __shared__ float Bs[8][128];
    int bm = blockIdx.y * 128, bn = blockIdx.x * 128;
    int tid = threadIdx.x;
    int tx = tid & 15, ty = tid >> 4;
    float acc[8][8];
#pragma unroll
    for (int i = 0; i < 8; i++)
#pragma unroll
        for (int j = 0; j < 8; j++) acc[i][j] = 0.f;

    for (int k0 = 0; k0 < K; k0 += 8) {
        {   // A tile: 128 rows x 8 k, one float4 per thread
            int m = tid >> 1, q = (tid & 1) * 4;
            float4 v = make_float4(0.f, 0.f, 0.f, 0.f);
            if (bm + m < M) v = *(const float4*)&g_h[(size_t)(bm + m) * K + k0 + q];
            As[q + 0][m] = v.x; As[q + 1][m] = v.y; As[q + 2][m] = v.z; As[q + 3][m] = v.w;
        }
#pragma unroll
        for (int r = 0; r < 4; r++) {   // B tile: 8 k x 128 cols
            int kk = (tid >> 7) + r * 2;
            int n = tid & 127;
            Bs[kk][n] = (bn + n < N) ? B[(size_t)(k0 + kk) * N + bn + n] : 0.f;
        }
        __syncthreads();
#pragma unroll
        for (int kk = 0; kk < 8; kk++) {
            float a[8], b[8];
            *(float4*)&a[0] = *(const float4*)&As[kk][ty * 8];
            *(float4*)&a[4] = *(const float4*)&As[kk][ty * 8 + 4];
            *(float4*)&b[0] = *(const float4*)&Bs[kk][tx * 8];
            *(float4*)&b[4] = *(const float4*)&Bs[kk][tx * 8 + 4];
#pragma unroll
            for (int i = 0; i < 8; i++)
#pragma unroll
                for (int j = 0; j < 8; j++) acc[i][j] = fmaf(a[i], b[j], acc[i][j]);
        }
        __syncthreads();
    }
#pragma unroll
    for (int i = 0; i < 8; i++) {
        int r = bm + ty * 8 + i;
        if (r >= M) continue;
#pragma unroll
        for (int j4 = 0; j4 < 2; j4++) {
            int c = bn + tx * 8 + j4 * 4;
            if (c < N)
                *(float4*)&g_xs[(size_t)r * N + c] =
                    make_float4(acc[i][j4 * 4], acc[i][j4 * 4 + 1], acc[i][j4 * 4 + 2], acc[i][j4 * 4 + 3]);
        }
    }
}

// ---------------- per-node alpha_s / alpha_d from g_xs (one warp per node) ----------------
template <int H>
__global__ void k_alpha_node(const float* __restrict__ asc, const float* __restrict__ adc) {
    int warp = (blockIdx.x * blockDim.x + threadIdx.x) >> 5;
    int l = threadIdx.x & 31;
    if (warp >= NN) return;
    const float* row = &g_xs[(size_t)warp * H * 32];
    float ps[H], pd[H];
#pragma unroll
    for (int h = 0; h < H; h++) {
        float v = row[h * 32 + l];
        ps[h] = v * asc[h * 32 + l];
        pd[h] = v * adc[h * 32 + l];
    }
#pragma unroll
    for (int h = 0; h < H; h++)
#pragma unroll
        for (int o = 16; o; o >>= 1) {
            ps[h] += __shfl_xor_sync(0xffffffffu, ps[h], o);
            pd[h] += __shfl_xor_sync(0xffffffffu, pd[h], o);
        }
    if (l == 0) {
#pragma unroll
        for (int h = 0; h < H; h++) {
            g_as[warp * H + h] = ps[h];
            g_ad[warp * H + h] = pd[h];
        }
    }
}

// ---------------- GAT softmax + aggregation, one warp per dst node ----------------
// reads g_xs, writes g_h. alpha_e inline: ae[e,h] = ea[e,:]·Me[:,h]
template <int H>
__global__ void k_aggregate(const float* __restrict__ ea,
                            const float* __restrict__ bias) {
    const int HC = H * 32;
    int warp = (blockIdx.x * blockDim.x + threadIdx.x) >> 5;
    int lane = threadIdx.x & 31;
    int wloc = threadIdx.x >> 5;
    if (warp >= NN) return;
    int n = warp;
    int beg = g_off[n], end = g_off[n + 1];

    float Me0[H], Me1[H], Me2[H], aesl[H], ad[H];
#pragma unroll
    for (int h = 0; h < H; h++) {
        Me0[h] = g_Me[h]; Me1[h] = g_Me[H + h]; Me2[h] = g_Me[2 * H + h];
        aesl[h] = g_aeself[h];
        ad[h] = g_ad[n * H + h];
    }

    // ---- pass 1: segment max (lane-strided) ----
    float mx[H];
#pragma unroll
    for (int h = 0; h < H; h++) mx[h] = -1e30f;
    for (int i = beg + lane; i < end; i += 32) {
        int s = g_srcs[i], e = g_eids[i];
        float e0 = 0.f, e1 = 0.f, e2 = 0.f; bool real = (e < NE);
        if (real) { e0 = ea[3 * e]; e1 = ea[3 * e + 1]; e2 = ea[3 * e + 2]; }
#pragma unroll
        for (int h = 0; h < H; h++) {
            float aev = real ? (e0 * Me0[h] + e1 * Me1[h] + e2 * Me2[h]) : aesl[h];
            float l = g_as[s * H + h] + ad[h] + aev;
            l = (l > 0.f) ? l : NEGS * l;
            mx[h] = fmaxf(mx[h], l);
        }
    }
#pragma unroll
    for (int h = 0; h < H; h++)
#pragma unroll
        for (int o = 16; o; o >>= 1) mx[h] = fmaxf(mx[h], __shfl_xor_sync(0xffffffffu, mx[h], o));

    // ---- pass 2: sum of exp ----
    float sm[H];
#pragma unroll
    for (int h = 0; h < H; h++) sm[h] = 0.f;
    for (int i = beg + lane; i < end; i += 32) {
        int s = g_srcs[i], e = g_eids[i];
        float e0 = 0.f, e1 = 0.f, e2 = 0.f; bool real = (e < NE);
        if (real) { e0 = ea[3 * e]; e1 = ea[3 * e + 1]; e2 = ea[3 * e + 2]; }
#pragma unroll
        for (int h = 0; h < H; h++) {
            float aev = real ? (e0 * Me0[h] + e1 * Me1[h] + e2 * Me2[h]) : aesl[h];
            float l = g_as[s * H + h] + ad[h] + aev;
            l = (l > 0.f) ? l : NEGS * l;
            sm[h] += __expf(l - mx[h]);
        }
    }
#pragma unroll
    for (int h = 0; h < H; h++)
#pragma unroll
        for (int o = 16; o; o >>= 1) sm[h] += __shfl_xor_sync(0xffffffffu, sm[h], o);

    float inv[H];
#pragma unroll
    for (int h = 0; h < H; h++) inv[h] = 1.f / (sm[h] + 1e-16f);

    // stash per-head max/inv in shared for lane-indexed access in pass 3
    __shared__ float s_mx[8][H], s_inv[8][H];
    if (lane == 0) {
#pragma unroll
        for (int h = 0; h < H; h++) { s_mx[wloc][h] = mx[h]; s_inv[wloc][h] = inv[h]; }
    }
    __syncwarp();
    float adl = 0.f, mxl = 0.f, invl = 0.f, m0l = 0.f, m1l = 0.f, m2l = 0.f, aesll = 0.f;
    if (lane < H) {
        adl = g_ad[n * H + lane]; mxl = s_mx[wloc][lane]; invl = s_inv[wloc][lane];
        m0l = g_Me[lane]; m1l = g_Me[H + lane]; m2l = g_Me[2 * H + lane];
        aesll = g_aeself[lane];
    }

    // ---- pass 3: weighted message accumulation (full warp per edge) ----
    float acc[H];
#pragma unroll
    for (int h = 0; h < H; h++) acc[h] = 0.f;
    for (int i = beg; i < end; i++) {
        int s = g_srcs[i], e = g_eids[i];
        bool real = (e < NE);
        float wv = 0.f;
        if (lane < H) {
            float aev;
            if (real) {
                float e0 = ea[3 * e], e1 = ea[3 * e + 1], e2 = ea[3 * e + 2];
                aev = e0 * m0l + e1 * m1l + e2 * m2l;
            } else aev = aesll;
            float l = g_as[s * H + lane] + adl + aev;
            l = (l > 0.f) ? l : NEGS * l;
            wv = __expf(l - mxl) * invl;
        }
        const float* row = &g_xs[(size_t)s * HC];
#pragma unroll
        for (int h = 0; h < H; h++) {
            float w = __shfl_sync(0xffffffffu, wv, h);
            acc[h] = fmaf(w, row[h * 32 + lane], acc[h]);
        }
    }
#pragma unroll
    for (int h = 0; h < H; h++) {
        float v = acc[h] + bias[h * 32 + lane];
        v = (v > 0.f) ? v : (__expf(v) - 1.f);   // ELU
        g_h[(size_t)n * HC + h * 32 + lane] = v;
    }
}

// ---------------- final edge MLP (reads g_h: 50000 x 32) ----------------
__global__ void k_mlp(const void* __restrict__ ei,
                      const float* __restrict__ mw1, const float* __restrict__ mb1,
                      const float* __restrict__ mw2, const float* __restrict__ mb2,
                      float* __restrict__ out) {
    __shared__ float w1s[2048], w2s[96], b1s[32], b2s[3];
    for (int i = threadIdx.x; i < 2048; i += blockDim.x) w1s[i] = mw1[i];
    for (int i = threadIdx.x; i < 96; i += blockDim.x) w2s[i] = mw2[i];
    if (threadIdx.x < 32) b1s[threadIdx.x] = mb1[threadIdx.x];
    if (threadIdx.x < 3) b2s[threadIdx.x] = mb2[threadIdx.x];
    __syncthreads();
    int e = blockIdx.x * blockDim.x + threadIdx.x;
    if (e >= NE) return;
    int is64 = g_idx64;
    int s = ld_idx(ei, e, is64), d = ld_idx(ei, (long long)NE + e, is64);

    float hid[32];
#pragma unroll
    for (int j = 0; j < 32; j++) hid[j] = b1s[j];

    const float4* rs = (const float4*)&g_h[s * 32];
    const float4* rd = (const float4*)&g_h[d * 32];
#pragma unroll
    for (int half = 0; half < 2; half++) {
        const float4* rp = half ? rd : rs;
#pragma unroll
        for (int i4 = 0; i4 < 8; i4++) {
            float4 v = rp[i4];
            float f[4] = {v.x, v.y, v.z, v.w};
#pragma unroll
            for (int c = 0; c < 4; c++) {
                int i = half * 32 + i4 * 4 + c;
                float fc = f[c];
#pragma unroll
                for (int j4 = 0; j4 < 8; j4++) {
                    float4 w = *(const float4*)&w1s[i * 32 + j4 * 4];
                    hid[j4 * 4 + 0] = fmaf(fc, w.x, hid[j4 * 4 + 0]);
                    hid[j4 * 4 + 1] = fmaf(fc, w.y, hid[j4 * 4 + 1]);
                    hid[j4 * 4 + 2] = fmaf(fc, w.z, hid[j4 * 4 + 2]);
                    hid[j4 * 4 + 3] = fmaf(fc, w.w, hid[j4 * 4 + 3]);
                }
            }
        }
    }
    float o0 = b2s[0], o1 = b2s[1], o2 = b2s[2];
#pragma unroll
    for (int j = 0; j < 32; j++) {
        float hj = fmaxf(hid[j], 0.f);
        o0 = fmaf(hj, w2s[j * 3 + 0], o0);
        o1 = fmaf(hj, w2s[j * 3 + 1], o1);
        o2 = fmaf(hj, w2s[j * 3 + 2], o2);
    }
    out[(size_t)e * 3 + 0] = o0;
    out[(size_t)e * 3 + 1] = o1;
    out[(size_t)e * 3 + 2] = o2;
}

// ---------------- launch (kernel launches ONLY — no runtime API) ----------------
extern "C" void kernel_launch(void* const* d_in, const int* in_sizes, int n_in,
                              void* d_out, int out_size) {
    const void*  x   = d_in[0];                   // int32 or int64 (detected on device)
    const void*  ei  = d_in[1];                   // int32 or int64 [2, NE]
    const float* ea  = (const float*)d_in[2];
    const float* emb = (const float*)d_in[3];
    const float* w0  = (const float*)d_in[4];
    const float* as0 = (const float*)d_in[5];
    const float* ad0 = (const float*)d_in[6];
    const float* we0 = (const float*)d_in[7];
    const float* ae0 = (const float*)d_in[8];
    const float* b0  = (const float*)d_in[9];
    const float* w1  = (const float*)d_in[10];
    const float* as1 = (const float*)d_in[11];
    const float* ad1 = (const float*)d_in[12];
    const float* we1 = (const float*)d_in[13];
    const float* ae1 = (const float*)d_in[14];
    const float* b1  = (const float*)d_in[15];
    const float* w2  = (const float*)d_in[16];
    const float* as2 = (const float*)d_in[17];
    const float* ad2 = (const float*)d_in[18];
    const float* we2 = (const float*)d_in[19];
    const float* ae2 = (const float*)d_in[20];
    const float* b2  = (const float*)d_in[21];
    const float* mw1 = (const float*)d_in[22];
    const float* mb1 = (const float*)d_in[23];
    const float* mw2 = (const float*)d_in[24];
    const float* mb2 = (const float*)d_in[25];
    float* out = (float*)d_out;

    // dtype detect + CSR build + embedding
    k_detect<<<1, 1>>>((const int*)ei);
    k_init<<<(NN + 255) / 256, 256>>>();
    k_edge_pre<<<(NE + 255) / 256, 256>>>(ei, ea);
    k_scan<<<1, 1024>>>();
    k_scatter<<<(ET + 255) / 256, 256>>>(ei);
    k_embed<<<(NN * 128 + 255) / 256, 256>>>(x, emb);

    const int aggGrid = (NN + 7) / 8;        // 8 warps / block

    // layer 0: K=128 -> HC=256
    k_prep<<<1, 32>>>(we0, ae0, 8);
    k_gemm<<<dim3(2, (NN + 127) / 128), 256>>>(w0, NN, 128, 256);
    k_alpha_node<8><<<aggGrid, 256>>>(as0, ad0);
    k_aggregate<8><<<aggGrid, 256>>>(ea, b0);

    // layer 1: 256 -> 256
    k_prep<<<1, 32>>>(we1, ae1, 8);
    k_gemm<<<dim3(2, (NN + 127) / 128), 256>>>(w1, NN, 256, 256);
    k_alpha_node<8><<<aggGrid, 256>>>(as1, ad1);
    k_aggregate<8><<<aggGrid, 256>>>(ea, b1);

    // layer 2: 256 -> 32, heads=1
    k_prep<<<1, 32>>>(we2, ae2, 1);
    k_gemm<<<dim3(1, (NN + 127) / 128), 256>>>(w2, NN, 256, 32);
    k_alpha_node<1><<<aggGrid, 256>>>(as2, ad2);
    k_aggregate<1><<<aggGrid, 256>>>(ea, b2);

    // final edge MLP
    k_mlp<<<(NE + 127) / 128, 128>>>(ei, mw1, mb1, mw2, mb2, out);
}

// round 8
// speedup vs baseline: 1.0642x; 1.0642x over previous
#include <cuda_runtime.h>

#define NN 50000
#define NE 800000
#define ET (NN + NE)          // 850000 edges incl self-loops
#define NEGS 0.2f

// ---------------- static scratch (no allocation allowed) ----------------
__device__ float g_h [NN * 256];      // layer input/output rows (stride = HC of layer)
__device__ float g_xs[NN * 256];      // xs = h @ W
__device__ float g_as[NN * 8];        // per-node alpha_src
__device__ float g_ad[NN * 8];        // per-node alpha_dst
__device__ float g_pre[NN * 64];      // MLP node pre-transforms: [n][0:32]=h@W1_top, [32:64]=h@W1_bot
__device__ int   g_deg[NN];
__device__ int   g_off[NN + 1];
__device__ int   g_cur[NN];
__device__ int   g_bsum[256];
__device__ int   g_srcs[ET];
__device__ int   g_eids[ET];
__device__ float g_Me[3 * 8];
__device__ float g_aeself[8];
__device__ float g_eacc[3];
__device__ int   g_idx64;             // 1 if indices are int64, 0 if int32

// index load helper: branch on runtime dtype flag, clamp to [0, NN)
__device__ __forceinline__ int ld_idx(const void* p, long long i, int is64) {
    int v;
    if (is64) v = (int)((const long long*)p)[i];
    else      v = ((const int*)p)[i];
    v = v < 0 ? 0 : (v >= NN ? NN - 1 : v);
    return v;
}

// ---------------- dtype detect: odd 32-bit words all zero => int64 ----------------
__global__ void k_detect(const int* __restrict__ ei_raw) {
    int allzero = 1;
    for (int i = 0; i < 64; i++)
        if (ei_raw[2 * i + 1] != 0) { allzero = 0; break; }
    g_idx64 = allzero;
}

// ---------------- init: deg=1 (self loop), zero mean accum ----------------
__global__ void k_init() {
    int t = blockIdx.x * blockDim.x + threadIdx.x;
    if (t < NN) g_deg[t] = 1;
    if (t < 3) g_eacc[t] = 0.f;
}

// ---------------- histogram of dst + edge_attr mean accumulation ----------------
__global__ void k_edge_pre(const void* __restrict__ ei, const float* __restrict__ ea) {
    int t = blockIdx.x * blockDim.x + threadIdx.x;
    int is64 = g_idx64;
    float a0 = 0.f, a1 = 0.f, a2 = 0.f;
    if (t < NE) {
        atomicAdd(&g_deg[ld_idx(ei, (long long)NE + t, is64)], 1);
        a0 = ea[3 * t]; a1 = ea[3 * t + 1]; a2 = ea[3 * t + 2];
    }
#pragma unroll
    for (int o = 16; o; o >>= 1) {
        a0 += __shfl_down_sync(0xffffffffu, a0, o);
        a1 += __shfl_down_sync(0xffffffffu, a1, o);
        a2 += __shfl_down_sync(0xffffffffu, a2, o);
    }
    __shared__ float s[3][8];
    int w = threadIdx.x >> 5;
    if ((threadIdx.x & 31) == 0) { s[0][w] = a0; s[1][w] = a1; s[2][w] = a2; }
    __syncthreads();
    if (threadIdx.x == 0) {
        float t0 = 0.f, t1 = 0.f, t2 = 0.f;
        for (int i = 0; i < 8; i++) { t0 += s[0][i]; t1 += s[1][i]; t2 += s[2][i]; }
        atomicAdd(&g_eacc[0], t0); atomicAdd(&g_eacc[1], t1); atomicAdd(&g_eacc[2], t2);
    }
}

// ---------------- multi-block exclusive scan of degrees ----------------
// 256 chunks x 256 nodes; A: per-chunk scan, B: scan of chunk sums, C: add base
__global__ void k_scanA() {
    __shared__ int s[256];
    int c = blockIdx.x, t = threadIdx.x;
    int n = c * 256 + t;
    int v = (n < NN) ? g_deg[n] : 0;
    s[t] = v;
    __syncthreads();
#pragma unroll
    for (int off = 1; off < 256; off <<= 1) {
        int x = (t >= off) ? s[t - off] : 0;
        __syncthreads();
        s[t] += x;
        __syncthreads();
    }
    if (n < NN) g_off[n] = s[t] - v;          // local exclusive prefix
    if (t == 255) g_bsum[c] = s[255];
}
__global__ void k_scanB() {
    __shared__ int s[256];
    int t = threadIdx.x;
    int v = g_bsum[t];
    s[t] = v;
    __syncthreads();
#pragma unroll
    for (int off = 1; off < 256; off <<= 1) {
        int x = (t >= off) ? s[t - off] : 0;
        __syncthreads();
        s[t] += x;
        __syncthreads();
    }
    g_bsum[t] = s[t] - v;                      // exclusive base per chunk
    if (t == 255) g_off[NN] = s[255];          // total
}
__global__ void k_scanC() {
    int c = blockIdx.x, t = threadIdx.x;
    int n = c * 256 + t;
    if (n < NN) {
        int o = g_off[n] + g_bsum[c];
        g_off[n] = o;
        g_cur[n] = o;
    }
}

// ---------------- scatter edges into CSR ----------------
__global__ void k_scatter(const void* __restrict__ ei) {
    int t = blockIdx.x * blockDim.x + threadIdx.x;
    if (t >= ET) return;
    int is64 = g_idx64;
    int src, dst;
    if (t < NE) { src = ld_idx(ei, t, is64); dst = ld_idx(ei, (long long)NE + t, is64); }
    else        { src = dst = t - NE; }
    int p = atomicAdd(&g_cur[dst], 1);
    if (p < ET) { g_srcs[p] = src; g_eids[p] = t; }
}

// ---------------- embedding lookup -> g_h ----------------
__global__ void k_embed(const void* __restrict__ x, const float* __restrict__ emb) {
    int t = blockIdx.x * blockDim.x + threadIdx.x;
    if (t >= NN * 128) return;
    int is64 = g_idx64;
    int n = t >> 7, d = t & 127;
    int v;
    if (is64) v = (int)((const long long*)x)[n];
    else      v = ((const int*)x)[n];
    v = v < 0 ? 0 : (v > 8 ? 8 : v);   // VOCAB=9
    g_h[n * 128 + d] = emb[v * 128 + d];
}

// ---------------- per-layer prep: Me[d][h] = sum_o We[d][h*32+o]*ae[h][o]; aeself ----------------
__global__ void k_prep(const float* __restrict__ We, const float* __restrict__ ae, int heads) {
    int t = threadIdx.x;
    if (t < 3 * heads) {
        int d = t / heads, h = t % heads;
        float s = 0.f;
        for (int o = 0; o < 32; o++) s += We[d * heads * 32 + h * 32 + o] * ae[h * 32 + o];
        g_Me[d * heads + h] = s;
    }
    __syncthreads();
    if (t < heads) {
        float s = 0.f;
        for (int d = 0; d < 3; d++) s += (g_eacc[d] * (1.f / NE)) * g_Me[d * heads + t];
        g_aeself[t] = s;
    }
}

// ---------------- tiled fp32 GEMM: g_xs[M,N] = g_h[M,K] @ B[K,N] ----------------
__global__ void k_gemm(const float* __restrict__ B, int M, int K, int N) {
    __shared__ float As[8][128];
    __shared__ float Bs[8][128];
    int bm = blockIdx.y * 128, bn = blockIdx.x * 128;
    int tid = threadIdx.x;
    int tx = tid & 15, ty = tid >> 4;
    float acc[8][8];
#pragma unroll
    for (int i = 0; i < 8; i++)
#pragma unroll
        for (int j = 0; j < 8; j++) acc[i][j] = 0.f;

    for (int k0 = 0; k0 < K; k0 += 8) {
        {
            int m = tid >> 1, q = (tid & 1) * 4;
            float4 v = make_float4(0.f, 0.f, 0.f, 0.f);
            if (bm + m < M) v = *(const float4*)&g_h[(size_t)(bm + m) * K + k0 + q];
            As[q + 0][m] = v.x; As[q + 1][m] = v.y; As[q + 2][m] = v.z; As[q + 3][m] = v.w;
        }
#pragma unroll
        for (int r = 0; r < 4; r++) {
            int kk = (tid >> 7) + r * 2;
            int n = tid & 127;
            Bs[kk][n] = (bn + n < N) ? B[(size_t)(k0 + kk) * N + bn + n] : 0.f;
        }
        __syncthreads();
#pragma unroll
        for (int kk = 0; kk < 8; kk++) {
            float a[8], b[8];
            *(float4*)&a[0] = *(const float4*)&As[kk][ty * 8];
            *(float4*)&a[4] = *(const float4*)&As[kk][ty * 8 + 4];
            *(float4*)&b[0] = *(const float4*)&Bs[kk][tx * 8];
            *(float4*)&b[4] = *(const float4*)&Bs[kk][tx * 8 + 4];
#pragma unroll
            for (int i = 0; i < 8; i++)
#pragma unroll
                for (int j = 0; j < 8; j++) acc[i][j] = fmaf(a[i], b[j], acc[i][j]);
        }
        __syncthreads();
    }
#pragma unroll
    for (int i = 0; i < 8; i++) {
        int r = bm + ty * 8 + i;
        if (r >= M) continue;
#pragma unroll
        for (int j4 = 0; j4 < 2; j4++) {
            int c = bn + tx * 8 + j4 * 4;
            if (c < N)
                *(float4*)&g_xs[(size_t)r * N + c] =
                    make_float4(acc[i][j4 * 4], acc[i][j4 * 4 + 1], acc[i][j4 * 4 + 2], acc[i][j4 * 4 + 3]);
        }
    }
}

// ---------------- per-node alpha_s / alpha_d from g_xs (one warp per node) ----------------
template <int H>
__global__ void k_alpha_node(const float* __restrict__ asc, const float* __restrict__ adc) {
    int warp = (blockIdx.x * blockDim.x + threadIdx.x) >> 5;
    int l = threadIdx.x & 31;
    if (warp >= NN) return;
    const float* row = &g_xs[(size_t)warp * H * 32];
    float ps[H], pd[H];
#pragma unroll
    for (int h = 0; h < H; h++) {
        float v = row[h * 32 + l];
        ps[h] = v * asc[h * 32 + l];
        pd[h] = v * adc[h * 32 + l];
    }
#pragma unroll
    for (int h = 0; h < H; h++)
#pragma unroll
        for (int o = 16; o; o >>= 1) {
            ps[h] += __shfl_xor_sync(0xffffffffu, ps[h], o);
            pd[h] += __shfl_xor_sync(0xffffffffu, pd[h], o);
        }
    if (l == 0) {
#pragma unroll
        for (int h = 0; h < H; h++) {
            g_as[warp * H + h] = ps[h];
            g_ad[warp * H + h] = pd[h];
        }
    }
}

// ---------------- GAT softmax + aggregation, one warp per dst node ----------------
// ONLINE softmax: single sweep for (max, sum), then weighted accumulation sweep.
template <int H>
__global__ void k_aggregate(const float* __restrict__ ea,
                            const float* __restrict__ bias) {
    const int HC = H * 32;
    int warp = (blockIdx.x * blockDim.x + threadIdx.x) >> 5;
    int lane = threadIdx.x & 31;
    int wloc = threadIdx.x >> 5;
    if (warp >= NN) return;
    int n = warp;
    int beg = g_off[n], end = g_off[n + 1];

    float Me0[H], Me1[H], Me2[H], aesl[H], ad[H];
#pragma unroll
    for (int h = 0; h < H; h++) {
        Me0[h] = g_Me[h]; Me1[h] = g_Me[H + h]; Me2[h] = g_Me[2 * H + h];
        aesl[h] = g_aeself[h];
        ad[h] = g_ad[n * H + h];
    }

    // ---- fused pass: online (max, sum-exp), lane-strided over edges ----
    float mx[H], sm[H];
#pragma unroll
    for (int h = 0; h < H; h++) { mx[h] = -1e30f; sm[h] = 0.f; }
    for (int i = beg + lane; i < end; i += 32) {
        int s = g_srcs[i], e = g_eids[i];
        float e0 = 0.f, e1 = 0.f, e2 = 0.f; bool real = (e < NE);
        if (real) { e0 = ea[3 * e]; e1 = ea[3 * e + 1]; e2 = ea[3 * e + 2]; }
#pragma unroll
        for (int h = 0; h < H; h++) {
            float aev = real ? (e0 * Me0[h] + e1 * Me1[h] + e2 * Me2[h]) : aesl[h];
            float l = g_as[s * H + h] + ad[h] + aev;
            l = (l > 0.f) ? l : NEGS * l;
            float mn = fmaxf(mx[h], l);
            sm[h] = sm[h] * __expf(mx[h] - mn) + __expf(l - mn);
            mx[h] = mn;
        }
    }
    // lane-merge of (m, s) pairs
#pragma unroll
    for (int o = 16; o; o >>= 1) {
#pragma unroll
        for (int h = 0; h < H; h++) {
            float mo = __shfl_xor_sync(0xffffffffu, mx[h], o);
            float so = __shfl_xor_sync(0xffffffffu, sm[h], o);
            float mn = fmaxf(mx[h], mo);
            sm[h] = sm[h] * __expf(mx[h] - mn) + so * __expf(mo - mn);
            mx[h] = mn;
        }
    }

    float inv[H];
#pragma unroll
    for (int h = 0; h < H; h++) inv[h] = 1.f / (sm[h] + 1e-16f);

    // stash per-head max/inv in shared for lane-indexed access in pass 2
    __shared__ float s_mx[8][H], s_inv[8][H];
    if (lane == 0) {
#pragma unroll
        for (int h = 0; h < H; h++) { s_mx[wloc][h] = mx[h]; s_inv[wloc][h] = inv[h]; }
    }
    __syncwarp();
    float adl = 0.f, mxl = 0.f, invl = 0.f, m0l = 0.f, m1l = 0.f, m2l = 0.f, aesll = 0.f;
    if (lane < H) {
        adl = g_ad[n * H + lane]; mxl = s_mx[wloc][lane]; invl = s_inv[wloc][lane];
        m0l = g_Me[lane]; m1l = g_Me[H + lane]; m2l = g_Me[2 * H + lane];
        aesll = g_aeself[lane];
    }

    // ---- pass 2: weighted message accumulation (full warp per edge) ----
    float acc[H];
#pragma unroll
    for (int h = 0; h < H; h++) acc[h] = 0.f;
    for (int i = beg; i < end; i++) {
        int s = g_srcs[i], e = g_eids[i];
        bool real = (e < NE);
        float wv = 0.f;
        if (lane < H) {
            float aev;
            if (real) {
                float e0 = ea[3 * e], e1 = ea[3 * e + 1], e2 = ea[3 * e + 2];
                aev = e0 * m0l + e1 * m1l + e2 * m2l;
            } else aev = aesll;
            float l = g_as[s * H + lane] + adl + aev;
            l = (l > 0.f) ? l : NEGS * l;
            wv = __expf(l - mxl) * invl;
        }
        const float* row = &g_xs[(size_t)s * HC];
#pragma unroll
        for (int h = 0; h < H; h++) {
            float w = __shfl_sync(0xffffffffu, wv, h);
            acc[h] = fmaf(w, row[h * 32 + lane], acc[h]);
        }
    }
#pragma unroll
    for (int h = 0; h < H; h++) {
        float v = acc[h] + bias[h * 32 + lane];
        v = (v > 0.f) ? v : (__expf(v) - 1.f);   // ELU
        g_h[(size_t)n * HC + h * 32 + lane] = v;
    }
}

// ---------------- MLP node pre-transforms: g_pre[n][q] (q=half*32+j) ----------------
// pre_top = h2 @ W1[0:32,:], pre_bot = h2 @ W1[32:64,:]
__global__ void k_mlp_pre(const float* __restrict__ mw1) {
    __shared__ float w1s[2048];
    for (int i = threadIdx.x; i < 2048; i += blockDim.x) w1s[i] = mw1[i];
    __syncthreads();
    int t = blockIdx.x * blockDim.x + threadIdx.x;
    if (t >= NN * 64) return;
    int n = t >> 6, q = t & 63;
    int half = q >> 5, j = q & 31;
    const float* hrow = &g_h[n * 32];
    float s = 0.f;
#pragma unroll
    for (int i = 0; i < 32; i++)
        s = fmaf(hrow[i], w1s[(half * 32 + i) * 32 + j], s);
    g_pre[n * 64 + q] = s;
}

// ---------------- final edge MLP: hid = pre_top[s] + pre_bot[d] + b1 ----------------
__global__ void k_mlp(const void* __restrict__ ei,
                      const float* __restrict__ mb1,
                      const float* __restrict__ mw2, const float* __restrict__ mb2,
                      float* __restrict__ out) {
    __shared__ float w2s[96], b1s[32], b2s[3];
    if (threadIdx.x < 96) w2s[threadIdx.x] = mw2[threadIdx.x];
    if (threadIdx.x < 32) b1s[threadIdx.x] = mb1[threadIdx.x];
    if (threadIdx.x < 3) b2s[threadIdx.x] = mb2[threadIdx.x];
    __syncthreads();
    int e = blockIdx.x * blockDim.x + threadIdx.x;
    if (e >= NE) return;
    int is64 = g_idx64;
    int s = ld_idx(ei, e, is64), d = ld_idx(ei, (long long)NE + e, is64);

    const float4* ps = (const float4*)&g_pre[s * 64];       // top half
    const float4* pd = (const float4*)&g_pre[d * 64 + 32];  // bottom half
    float o0 = b2s[0], o1 = b2s[1], o2 = b2s[2];
#pragma unroll
    for (int i4 = 0; i4 < 8; i4++) {
        float4 a = ps[i4];
        float4 b = pd[i4];
        float hj;
        int j = i4 * 4;
        hj = fmaxf(a.x + b.x + b1s[j + 0], 0.f);
        o0 = fmaf(hj, w2s[(j + 0) * 3 + 0], o0); o1 = fmaf(hj, w2s[(j + 0) * 3 + 1], o1); o2 = fmaf(hj, w2s[(j + 0) * 3 + 2], o2);
        hj = fmaxf(a.y + b.y + b1s[j + 1], 0.f);
        o0 = fmaf(hj, w2s[(j + 1) * 3 + 0], o0); o1 = fmaf(hj, w2s[(j + 1) * 3 + 1], o1); o2 = fmaf(hj, w2s[(j + 1) * 3 + 2], o2);
        hj = fmaxf(a.z + b.z + b1s[j + 2], 0.f);
        o0 = fmaf(hj, w2s[(j + 2) * 3 + 0], o0); o1 = fmaf(hj, w2s[(j + 2) * 3 + 1], o1); o2 = fmaf(hj, w2s[(j + 2) * 3 + 2], o2);
        hj = fmaxf(a.w + b.w + b1s[j + 3], 0.f);
        o0 = fmaf(hj, w2s[(j + 3) * 3 + 0], o0); o1 = fmaf(hj, w2s[(j + 3) * 3 + 1], o1); o2 = fmaf(hj, w2s[(j + 3) * 3 + 2], o2);
    }
    out[(size_t)e * 3 + 0] = o0;
    out[(size_t)e * 3 + 1] = o1;
    out[(size_t)e * 3 + 2] = o2;
}

// ---------------- launch (kernel launches ONLY — no runtime API) ----------------
extern "C" void kernel_launch(void* const* d_in, const int* in_sizes, int n_in,
                              void* d_out, int out_size) {
    const void*  x   = d_in[0];                   // int32 or int64 (detected on device)
    const void*  ei  = d_in[1];                   // int32 or int64 [2, NE]
    const float* ea  = (const float*)d_in[2];
    const float* emb = (const float*)d_in[3];
    const float* w0  = (const float*)d_in[4];
    const float* as0 = (const float*)d_in[5];
    const float* ad0 = (const float*)d_in[6];
    const float* we0 = (const float*)d_in[7];
    const float* ae0 = (const float*)d_in[8];
    const float* b0  = (const float*)d_in[9];
    const float* w1  = (const float*)d_in[10];
    const float* as1 = (const float*)d_in[11];
    const float* ad1 = (const float*)d_in[12];
    const float* we1 = (const float*)d_in[13];
    const float* ae1 = (const float*)d_in[14];
    const float* b1  = (const float*)d_in[15];
    const float* w2  = (const float*)d_in[16];
    const float* as2 = (const float*)d_in[17];
    const float* ad2 = (const float*)d_in[18];
    const float* we2 = (const float*)d_in[19];
    const float* ae2 = (const float*)d_in[20];
    const float* b2  = (const float*)d_in[21];
    const float* mw1 = (const float*)d_in[22];
    const float* mb1 = (const float*)d_in[23];
    const float* mw2 = (const float*)d_in[24];
    const float* mb2 = (const float*)d_in[25];
    float* out = (float*)d_out;

    // dtype detect + CSR build + embedding
    k_detect<<<1, 1>>>((const int*)ei);
    k_init<<<(NN + 255) / 256, 256>>>();
    k_edge_pre<<<(NE + 255) / 256, 256>>>(ei, ea);
    k_scanA<<<256, 256>>>();
    k_scanB<<<1, 256>>>();
    k_scanC<<<256, 256>>>();
    k_scatter<<<(ET + 255) / 256, 256>>>(ei);
    k_embed<<<(NN * 128 + 255) / 256, 256>>>(x, emb);

    const int aggGrid = (NN + 7) / 8;        // 8 warps / block

    // layer 0: K=128 -> HC=256
    k_prep<<<1, 32>>>(we0, ae0, 8);
    k_gemm<<<dim3(2, (NN + 127) / 128), 256>>>(w0, NN, 128, 256);
    k_alpha_node<8><<<aggGrid, 256>>>(as0, ad0);
    k_aggregate<8><<<aggGrid, 256>>>(ea, b0);

    // layer 1: 256 -> 256
    k_prep<<<1, 32>>>(we1, ae1, 8);
    k_gemm<<<dim3(2, (NN + 127) / 128), 256>>>(w1, NN, 256, 256);
    k_alpha_node<8><<<aggGrid, 256>>>(as1, ad1);
    k_aggregate<8><<<aggGrid, 256>>>(ea, b1);

    // layer 2: 256 -> 32, heads=1
    k_prep<<<1, 32>>>(we2, ae2, 1);
    k_gemm<<<dim3(1, (NN + 127) / 128), 256>>>(w2, NN, 256, 32);
    k_alpha_node<1><<<aggGrid, 256>>>(as2, ad2);
    k_aggregate<1><<<aggGrid, 256>>>(ea, b2);

    // final edge MLP (factorized)
    k_mlp_pre<<<(NN * 64 + 255) / 256, 256>>>(mw1);
    k_mlp<<<(NE + 127) / 128, 128>>>(ei, mb1, mw2, mb2, out);
}

// round 9
// speedup vs baseline: 1.2251x; 1.1512x over previous
#include <cuda_runtime.h>
#include <cstdint>

#define NN 50000
#define NE 800000
#define ET (NN + NE)          // 850000 edges incl self-loops
#define NEGS 0.2f

// ---------------- static scratch (no allocation allowed) ----------------
__device__ float g_h [NN * 256];      // layer input/output rows (stride = HC of layer)
__device__ float g_xs[NN * 256];      // xs = h @ W
__device__ float g_as[NN * 8];        // per-node alpha_src
__device__ float g_ad[NN * 8];        // per-node alpha_dst
__device__ float g_pre[NN * 64];      // MLP node pre-transforms
__device__ int   g_deg[NN];
__device__ int   g_off[NN + 1];
__device__ int   g_cur[NN];
__device__ int   g_bsum[256];
__device__ int   g_srcs[ET];
__device__ int   g_eids[ET];
__device__ float g_Me[3 * 8];
__device__ float g_aeself[8];
__device__ float g_eacc[3];
__device__ int   g_idx64;             // 1 if indices are int64, 0 if int32

// index load helper: branch on runtime dtype flag, clamp to [0, NN)
__device__ __forceinline__ int ld_idx(const void* p, long long i, int is64) {
    int v;
    if (is64) v = (int)((const long long*)p)[i];
    else      v = ((const int*)p)[i];
    v = v < 0 ? 0 : (v >= NN ? NN - 1 : v);
    return v;
}

__device__ __forceinline__ uint32_t f2tf32(float x) {
    uint32_t t;
    asm("cvt.rna.tf32.f32 %0, %1;" : "=r"(t) : "f"(x));
    return t;
}

// ---------------- dtype detect ----------------
__global__ void k_detect(const int* __restrict__ ei_raw) {
    int allzero = 1;
    for (int i = 0; i < 64; i++)
        if (ei_raw[2 * i + 1] != 0) { allzero = 0; break; }
    g_idx64 = allzero;
}

// ---------------- init ----------------
__global__ void k_init() {
    int t = blockIdx.x * blockDim.x + threadIdx.x;
    if (t < NN) g_deg[t] = 1;
    if (t < 3) g_eacc[t] = 0.f;
}

// ---------------- histogram of dst + edge_attr mean ----------------
__global__ void k_edge_pre(const void* __restrict__ ei, const float* __restrict__ ea) {
    int t = blockIdx.x * blockDim.x + threadIdx.x;
    int is64 = g_idx64;
    float a0 = 0.f, a1 = 0.f, a2 = 0.f;
    if (t < NE) {
        atomicAdd(&g_deg[ld_idx(ei, (long long)NE + t, is64)], 1);
        a0 = ea[3 * t]; a1 = ea[3 * t + 1]; a2 = ea[3 * t + 2];
    }
#pragma unroll
    for (int o = 16; o; o >>= 1) {
        a0 += __shfl_down_sync(0xffffffffu, a0, o);
        a1 += __shfl_down_sync(0xffffffffu, a1, o);
        a2 += __shfl_down_sync(0xffffffffu, a2, o);
    }
    __shared__ float s[3][8];
    int w = threadIdx.x >> 5;
    if ((threadIdx.x & 31) == 0) { s[0][w] = a0; s[1][w] = a1; s[2][w] = a2; }
    __syncthreads();
    if (threadIdx.x == 0) {
        float t0 = 0.f, t1 = 0.f, t2 = 0.f;
        for (int i = 0; i < 8; i++) { t0 += s[0][i]; t1 += s[1][i]; t2 += s[2][i]; }
        atomicAdd(&g_eacc[0], t0); atomicAdd(&g_eacc[1], t1); atomicAdd(&g_eacc[2], t2);
    }
}

// ---------------- multi-block exclusive scan ----------------
__global__ void k_scanA() {
    __shared__ int s[256];
    int c = blockIdx.x, t = threadIdx.x;
    int n = c * 256 + t;
    int v = (n < NN) ? g_deg[n] : 0;
    s[t] = v;
    __syncthreads();
#pragma unroll
    for (int off = 1; off < 256; off <<= 1) {
        int x = (t >= off) ? s[t - off] : 0;
        __syncthreads();
        s[t] += x;
        __syncthreads();
    }
    if (n < NN) g_off[n] = s[t] - v;
    if (t == 255) g_bsum[c] = s[255];
}
__global__ void k_scanB() {
    __shared__ int s[256];
    int t = threadIdx.x;
    int v = g_bsum[t];
    s[t] = v;
    __syncthreads();
#pragma unroll
    for (int off = 1; off < 256; off <<= 1) {
        int x = (t >= off) ? s[t - off] : 0;
        __syncthreads();
        s[t] += x;
        __syncthreads();
    }
    g_bsum[t] = s[t] - v;
    if (t == 255) g_off[NN] = s[255];
}
__global__ void k_scanC() {
    int c = blockIdx.x, t = threadIdx.x;
    int n = c * 256 + t;
    if (n < NN) {
        int o = g_off[n] + g_bsum[c];
        g_off[n] = o;
        g_cur[n] = o;
    }
}

// ---------------- scatter edges into CSR ----------------
__global__ void k_scatter(const void* __restrict__ ei) {
    int t = blockIdx.x * blockDim.x + threadIdx.x;
    if (t >= ET) return;
    int is64 = g_idx64;
    int src, dst;
    if (t < NE) { src = ld_idx(ei, t, is64); dst = ld_idx(ei, (long long)NE + t, is64); }
    else        { src = dst = t - NE; }
    int p = atomicAdd(&g_cur[dst], 1);
    if (p < ET) { g_srcs[p] = src; g_eids[p] = t; }
}

// ---------------- embedding lookup -> g_h ----------------
__global__ void k_embed(const void* __restrict__ x, const float* __restrict__ emb) {
    int t = blockIdx.x * blockDim.x + threadIdx.x;
    if (t >= NN * 128) return;
    int is64 = g_idx64;
    int n = t >> 7, d = t & 127;
    int v;
    if (is64) v = (int)((const long long*)x)[n];
    else      v = ((const int*)x)[n];
    v = v < 0 ? 0 : (v > 8 ? 8 : v);   // VOCAB=9
    g_h[n * 128 + d] = emb[v * 128 + d];
}

// ---------------- per-layer prep ----------------
__global__ void k_prep(const float* __restrict__ We, const float* __restrict__ ae, int heads) {
    int t = threadIdx.x;
    if (t < 3 * heads) {
        int d = t / heads, h = t % heads;
        float s = 0.f;
        for (int o = 0; o < 32; o++) s += We[d * heads * 32 + h * 32 + o] * ae[h * 32 + o];
        g_Me[d * heads + h] = s;
    }
    __syncthreads();
    if (t < heads) {
        float s = 0.f;
        for (int d = 0; d < 3; d++) s += (g_eacc[d] * (1.f / NE)) * g_Me[d * heads + t];
        g_aeself[t] = s;
    }
}

// ---------------- TF32 tensor-core GEMM: g_xs[M,N] = g_h[M,K] @ B[K,N] ----------------
// BM=128 BN=128 BK=16; 256 threads = 8 warps (4m x 2n); warp tile 32x64
// mma.sync.aligned.m16n8k8.row.col.f32.tf32.tf32.f32
#define SA 20     // As row stride (floats), conflict-free for A-fragment pattern
#define SB 136    // Bs row stride (136%32==8 -> conflict-free B-fragment pattern)
__global__ void k_gemm_tc(const float* __restrict__ B, int M, int K, int N) {
    __shared__ uint32_t As[128 * SA];   // [m][k] tf32
    __shared__ uint32_t Bs[16 * SB];    // [k][n] tf32
    int tid = threadIdx.x;
    int lane = tid & 31, warp = tid >> 5;
    int wm = (warp & 3) * 32;           // warp m offset
    int wn = (warp >> 2) * 64;          // warp n offset
    int bm = blockIdx.y * 128, bn = blockIdx.x * 128;
    int lr = lane >> 2, lc = lane & 3;  // fragment row group / col-in-group

    float c[2][8][4];
#pragma unroll
    for (int mt = 0; mt < 2; mt++)
#pragma unroll
        for (int nt = 0; nt < 8; nt++)
#pragma unroll
            for (int q = 0; q < 4; q++) c[mt][nt][q] = 0.f;

    for (int k0 = 0; k0 < K; k0 += 16) {
        // load A tile: 128 rows x 16 k = 512 float4
#pragma unroll
        for (int r = 0; r < 2; r++) {
            int idx = tid + r * 256;
            int m = idx >> 2;
            int kq = (idx & 3) * 4;
            float4 v = make_float4(0.f, 0.f, 0.f, 0.f);
            if (bm + m < M) v = *(const float4*)&g_h[(size_t)(bm + m) * K + k0 + kq];
            As[m * SA + kq + 0] = f2tf32(v.x);
            As[m * SA + kq + 1] = f2tf32(v.y);
            As[m * SA + kq + 2] = f2tf32(v.z);
            As[m * SA + kq + 3] = f2tf32(v.w);
        }
        // load B tile: 16 k x 128 n = 512 float4
#pragma unroll
        for (int r = 0; r < 2; r++) {
            int idx = tid + r * 256;
            int kk = idx >> 5;
            int nq = (idx & 31) * 4;
            float4 v = make_float4(0.f, 0.f, 0.f, 0.f);
            if (bn + nq < N) v = *(const float4*)&B[(size_t)(k0 + kk) * N + bn + nq];
            Bs[kk * SB + nq + 0] = f2tf32(v.x);
            Bs[kk * SB + nq + 1] = f2tf32(v.y);
            Bs[kk * SB + nq + 2] = f2tf32(v.z);
            Bs[kk * SB + nq + 3] = f2tf32(v.w);
        }
        __syncthreads();
#pragma unroll
        for (int ks = 0; ks < 16; ks += 8) {
            uint32_t a[2][4];
#pragma unroll
            for (int mt = 0; mt < 2; mt++) {
                int r0 = wm + mt * 16 + lr;
                a[mt][0] = As[(r0) * SA + ks + lc];
                a[mt][1] = As[(r0 + 8) * SA + ks + lc];
                a[mt][2] = As[(r0) * SA + ks + lc + 4];
                a[mt][3] = As[(r0 + 8) * SA + ks + lc + 4];
            }
            uint32_t b[8][2];
#pragma unroll
            for (int nt = 0; nt < 8; nt++) {
                int cn = wn + nt * 8 + lr;
                b[nt][0] = Bs[(ks + lc) * SB + cn];
                b[nt][1] = Bs[(ks + lc + 4) * SB + cn];
            }
#pragma unroll
            for (int mt = 0; mt < 2; mt++)
#pragma unroll
                for (int nt = 0; nt < 8; nt++) {
                    asm volatile(
                        "mma.sync.aligned.m16n8k8.row.col.f32.tf32.tf32.f32 "
                        "{%0,%1,%2,%3}, {%4,%5,%6,%7}, {%8,%9}, {%0,%1,%2,%3};\n"
                        : "+f"(c[mt][nt][0]), "+f"(c[mt][nt][1]),
                          "+f"(c[mt][nt][2]), "+f"(c[mt][nt][3])
                        : "r"(a[mt][0]), "r"(a[mt][1]), "r"(a[mt][2]), "r"(a[mt][3]),
                          "r"(b[nt][0]), "r"(b[nt][1]));
                }
        }
        __syncthreads();
    }
    // store C
#pragma unroll
    for (int mt = 0; mt < 2; mt++) {
#pragma unroll
        for (int nt = 0; nt < 8; nt++) {
            int r0 = bm + wm + mt * 16 + lr;
            int cc = bn + wn + nt * 8 + 2 * lc;
            if (cc < N) {
                if (r0 < M) {
                    g_xs[(size_t)r0 * N + cc]     = c[mt][nt][0];
                    g_xs[(size_t)r0 * N + cc + 1] = c[mt][nt][1];
                }
                if (r0 + 8 < M) {
                    g_xs[(size_t)(r0 + 8) * N + cc]     = c[mt][nt][2];
                    g_xs[(size_t)(r0 + 8) * N + cc + 1] = c[mt][nt][3];
                }
            }
        }
    }
}

// ---------------- SIMT fp32 GEMM (kept for N=32 layer) ----------------
__global__ void k_gemm(const float* __restrict__ B, int M, int K, int N) {
    __shared__ float As2[8][128];
    __shared__ float Bs2[8][128];
    int bm = blockIdx.y * 128, bn = blockIdx.x * 128;
    int tid = threadIdx.x;
    int tx = tid & 15, ty = tid >> 4;
    float acc[8][8];
#pragma unroll
    for (int i = 0; i < 8; i++)
#pragma unroll
        for (int j = 0; j < 8; j++) acc[i][j] = 0.f;

    for (int k0 = 0; k0 < K; k0 += 8) {
        {
            int m = tid >> 1, q = (tid & 1) * 4;
            float4 v = make_float4(0.f, 0.f, 0.f, 0.f);
            if (bm + m < M) v = *(const float4*)&g_h[(size_t)(bm + m) * K + k0 + q];
            As2[q + 0][m] = v.x; As2[q + 1][m] = v.y; As2[q + 2][m] = v.z; As2[q + 3][m] = v.w;
        }
#pragma unroll
        for (int r = 0; r < 4; r++) {
            int kk = (tid >> 7) + r * 2;
            int n = tid & 127;
            Bs2[kk][n] = (bn + n < N) ? B[(size_t)(k0 + kk) * N + bn + n] : 0.f;
        }
        __syncthreads();
#pragma unroll
        for (int kk = 0; kk < 8; kk++) {
            float a[8], b[8];
            *(float4*)&a[0] = *(const float4*)&As2[kk][ty * 8];
            *(float4*)&a[4] = *(const float4*)&As2[kk][ty * 8 + 4];
            *(float4*)&b[0] = *(const float4*)&Bs2[kk][tx * 8];
            *(float4*)&b[4] = *(const float4*)&Bs2[kk][tx * 8 + 4];
#pragma unroll
            for (int i = 0; i < 8; i++)
#pragma unroll
                for (int j = 0; j < 8; j++) acc[i][j] = fmaf(a[i], b[j], acc[i][j]);
        }
        __syncthreads();
    }
#pragma unroll
    for (int i = 0; i < 8; i++) {
        int r = bm + ty * 8 + i;
        if (r >= M) continue;
#pragma unroll
        for (int j4 = 0; j4 < 2; j4++) {
            int c = bn + tx * 8 + j4 * 4;
            if (c < N)
                *(float4*)&g_xs[(size_t)r * N + c] =
                    make_float4(acc[i][j4 * 4], acc[i][j4 * 4 + 1], acc[i][j4 * 4 + 2], acc[i][j4 * 4 + 3]);
        }
    }
}

// ---------------- per-node alpha_s / alpha_d ----------------
template <int H>
__global__ void k_alpha_node(const float* __restrict__ asc, const float* __restrict__ adc) {
    int warp = (blockIdx.x * blockDim.x + threadIdx.x) >> 5;
    int l = threadIdx.x & 31;
    if (warp >= NN) return;
    const float* row = &g_xs[(size_t)warp * H * 32];
    float ps[H], pd[H];
#pragma unroll
    for (int h = 0; h < H; h++) {
        float v = row[h * 32 + l];
        ps[h] = v * asc[h * 32 + l];
        pd[h] = v * adc[h * 32 + l];
    }
#pragma unroll
    for (int h = 0; h < H; h++)
#pragma unroll
        for (int o = 16; o; o >>= 1) {
            ps[h] += __shfl_xor_sync(0xffffffffu, ps[h], o);
            pd[h] += __shfl_xor_sync(0xffffffffu, pd[h], o);
        }
    if (l == 0) {
#pragma unroll
        for (int h = 0; h < H; h++) {
            g_as[warp * H + h] = ps[h];
            g_ad[warp * H + h] = pd[h];
        }
    }
}

// ---------------- GAT softmax + aggregation ----------------
template <int H>
__global__ void k_aggregate(const float* __restrict__ ea,
                            const float* __restrict__ bias) {
    const int HC = H * 32;
    int warp = (blockIdx.x * blockDim.x + threadIdx.x) >> 5;
    int lane = threadIdx.x & 31;
    int wloc = threadIdx.x >> 5;
    if (warp >= NN) return;
    int n = warp;
    int beg = g_off[n], end = g_off[n + 1];

    float Me0[H], Me1[H], Me2[H], aesl[H], ad[H];
#pragma unroll
    for (int h = 0; h < H; h++) {
        Me0[h] = g_Me[h]; Me1[h] = g_Me[H + h]; Me2[h] = g_Me[2 * H + h];
        aesl[h] = g_aeself[h];
        ad[h] = g_ad[n * H + h];
    }

    float mx[H], sm[H];
#pragma unroll
    for (int h = 0; h < H; h++) { mx[h] = -1e30f; sm[h] = 0.f; }
    for (int i = beg + lane; i < end; i += 32) {
        int s = g_srcs[i], e = g_eids[i];
        float e0 = 0.f, e1 = 0.f, e2 = 0.f; bool real = (e < NE);
        if (real) { e0 = ea[3 * e]; e1 = ea[3 * e + 1]; e2 = ea[3 * e + 2]; }
#pragma unroll
        for (int h = 0; h < H; h++) {
            float aev = real ? (e0 * Me0[h] + e1 * Me1[h] + e2 * Me2[h]) : aesl[h];
            float l = g_as[s * H + h] + ad[h] + aev;
            l = (l > 0.f) ? l : NEGS * l;
            float mn = fmaxf(mx[h], l);
            sm[h] = sm[h] * __expf(mx[h] - mn) + __expf(l - mn);
            mx[h] = mn;
        }
    }
#pragma unroll
    for (int o = 16; o; o >>= 1) {
#pragma unroll
        for (int h = 0; h < H; h++) {
            float mo = __shfl_xor_sync(0xffffffffu, mx[h], o);
            float so = __shfl_xor_sync(0xffffffffu, sm[h], o);
            float mn = fmaxf(mx[h], mo);
            sm[h] = sm[h] * __expf(mx[h] - mn) + so * __expf(mo - mn);
            mx[h] = mn;
        }
    }

    float inv[H];
#pragma unroll
    for (int h = 0; h < H; h++) inv[h] = 1.f / (sm[h] + 1e-16f);

    __shared__ float s_mx[8][H], s_inv[8][H];
    if (lane == 0) {
#pragma unroll
        for (int h = 0; h < H; h++) { s_mx[wloc][h] = mx[h]; s_inv[wloc][h] = inv[h]; }
    }
    __syncwarp();
    float adl = 0.f, mxl = 0.f, invl = 0.f, m0l = 0.f, m1l = 0.f, m2l = 0.f, aesll = 0.f;
    if (lane < H) {
        adl = g_ad[n * H + lane]; mxl = s_mx[wloc][lane]; invl = s_inv[wloc][lane];
        m0l = g_Me[lane]; m1l = g_Me[H + lane]; m2l = g_Me[2 * H + lane];
        aesll = g_aeself[lane];
    }

    float acc[H];
#pragma unroll
    for (int h = 0; h < H; h++) acc[h] = 0.f;
    for (int i = beg; i < end; i++) {
        int s = g_srcs[i], e = g_eids[i];
        bool real = (e < NE);
        float wv = 0.f;
        if (lane < H) {
            float aev;
            if (real) {
                float e0 = ea[3 * e], e1 = ea[3 * e + 1], e2 = ea[3 * e + 2];
                aev = e0 * m0l + e1 * m1l + e2 * m2l;
            } else aev = aesll;
            float l = g_as[s * H + lane] + adl + aev;
            l = (l > 0.f) ? l : NEGS * l;
            wv = __expf(l - mxl) * invl;
        }
        const float* row = &g_xs[(size_t)s * HC];
#pragma unroll
        for (int h = 0; h < H; h++) {
            float w = __shfl_sync(0xffffffffu, wv, h);
            acc[h] = fmaf(w, row[h * 32 + lane], acc[h]);
        }
    }
#pragma unroll
    for (int h = 0; h < H; h++) {
        float v = acc[h] + bias[h * 32 + lane];
        v = (v > 0.f) ? v : (__expf(v) - 1.f);   // ELU
        g_h[(size_t)n * HC + h * 32 + lane] = v;
    }
}

// ---------------- MLP node pre-transforms ----------------
__global__ void k_mlp_pre(const float* __restrict__ mw1) {
    __shared__ float w1s[2048];
    for (int i = threadIdx.x; i < 2048; i += blockDim.x) w1s[i] = mw1[i];
    __syncthreads();
    int t = blockIdx.x * blockDim.x + threadIdx.x;
    if (t >= NN * 64) return;
    int n = t >> 6, q = t & 63;
    int half = q >> 5, j = q & 31;
    const float* hrow = &g_h[n * 32];
    float s = 0.f;
#pragma unroll
    for (int i = 0; i < 32; i++)
        s = fmaf(hrow[i], w1s[(half * 32 + i) * 32 + j], s);
    g_pre[n * 64 + q] = s;
}

// ---------------- final edge MLP ----------------
__global__ void k_mlp(const void* __restrict__ ei,
                      const float* __restrict__ mb1,
                      const float* __restrict__ mw2, const float* __restrict__ mb2,
                      float* __restrict__ out) {
    __shared__ float w2s[96], b1s[32], b2s[3];
    if (threadIdx.x < 96) w2s[threadIdx.x] = mw2[threadIdx.x];
    if (threadIdx.x < 32) b1s[threadIdx.x] = mb1[threadIdx.x];
    if (threadIdx.x < 3) b2s[threadIdx.x] = mb2[threadIdx.x];
    __syncthreads();
    int e = blockIdx.x * blockDim.x + threadIdx.x;
    if (e >= NE) return;
    int is64 = g_idx64;
    int s = ld_idx(ei, e, is64), d = ld_idx(ei, (long long)NE + e, is64);

    const float4* ps = (const float4*)&g_pre[s * 64];
    const float4* pd = (const float4*)&g_pre[d * 64 + 32];
    float o0 = b2s[0], o1 = b2s[1], o2 = b2s[2];
#pragma unroll
    for (int i4 = 0; i4 < 8; i4++) {
        float4 a = ps[i4];
        float4 b = pd[i4];
        float hj;
        int j = i4 * 4;
        hj = fmaxf(a.x + b.x + b1s[j + 0], 0.f);
        o0 = fmaf(hj, w2s[(j + 0) * 3 + 0], o0); o1 = fmaf(hj, w2s[(j + 0) * 3 + 1], o1); o2 = fmaf(hj, w2s[(j + 0) * 3 + 2], o2);
        hj = fmaxf(a.y + b.y + b1s[j + 1], 0.f);
        o0 = fmaf(hj, w2s[(j + 1) * 3 + 0], o0); o1 = fmaf(hj, w2s[(j + 1) * 3 + 1], o1); o2 = fmaf(hj, w2s[(j + 1) * 3 + 2], o2);
        hj = fmaxf(a.z + b.z + b1s[j + 2], 0.f);
        o0 = fmaf(hj, w2s[(j + 2) * 3 + 0], o0); o1 = fmaf(hj, w2s[(j + 2) * 3 + 1], o1); o2 = fmaf(hj, w2s[(j + 2) * 3 + 2], o2);
        hj = fmaxf(a.w + b.w + b1s[j + 3], 0.f);
        o0 = fmaf(hj, w2s[(j + 3) * 3 + 0], o0); o1 = fmaf(hj, w2s[(j + 3) * 3 + 1], o1); o2 = fmaf(hj, w2s[(j + 3) * 3 + 2], o2);
    }
    out[(size_t)e * 3 + 0] = o0;
    out[(size_t)e * 3 + 1] = o1;
    out[(size_t)e * 3 + 2] = o2;
}

// ---------------- launch (kernel launches ONLY) ----------------
extern "C" void kernel_launch(void* const* d_in, const int* in_sizes, int n_in,
                              void* d_out, int out_size) {
    const void*  x   = d_in[0];
    const void*  ei  = d_in[1];
    const float* ea  = (const float*)d_in[2];
    const float* emb = (const float*)d_in[3];
    const float* w0  = (const float*)d_in[4];
    const float* as0 = (const float*)d_in[5];
    const float* ad0 = (const float*)d_in[6];
    const float* we0 = (const float*)d_in[7];
    const float* ae0 = (const float*)d_in[8];
    const float* b0  = (const float*)d_in[9];
    const float* w1  = (const float*)d_in[10];
    const float* as1 = (const float*)d_in[11];
    const float* ad1 = (const float*)d_in[12];
    const float* we1 = (const float*)d_in[13];
    const float* ae1 = (const float*)d_in[14];
    const float* b1  = (const float*)d_in[15];
    const float* w2  = (const float*)d_in[16];
    const float* as2 = (const float*)d_in[17];
    const float* ad2 = (const float*)d_in[18];
    const float* we2 = (const float*)d_in[19];
    const float* ae2 = (const float*)d_in[20];
    const float* b2  = (const float*)d_in[21];
    const float* mw1 = (const float*)d_in[22];
    const float* mb1 = (const float*)d_in[23];
    const float* mw2 = (const float*)d_in[24];
    const float* mb2 = (const float*)d_in[25];
    float* out = (float*)d_out;

    // dtype detect + CSR build + embedding
    k_detect<<<1, 1>>>((const int*)ei);
    k_init<<<(NN + 255) / 256, 256>>>();
    k_edge_pre<<<(NE + 255) / 256, 256>>>(ei, ea);
    k_scanA<<<256, 256>>>();
    k_scanB<<<1, 256>>>();
    k_scanC<<<256, 256>>>();
    k_scatter<<<(ET + 255) / 256, 256>>>(ei);
    k_embed<<<(NN * 128 + 255) / 256, 256>>>(x, emb);

    const int aggGrid = (NN + 7) / 8;        // 8 warps / block
    const dim3 tcGrid(2, (NN + 127) / 128);

    // layer 0: K=128 -> HC=256  (tensor core)
    k_prep<<<1, 32>>>(we0, ae0, 8);
    k_gemm_tc<<<tcGrid, 256>>>(w0, NN, 128, 256);
    k_alpha_node<8><<<aggGrid, 256>>>(as0, ad0);
    k_aggregate<8><<<aggGrid, 256>>>(ea, b0);

    // layer 1: 256 -> 256  (tensor core)
    k_prep<<<1, 32>>>(we1, ae1, 8);
    k_gemm_tc<<<tcGrid, 256>>>(w1, NN, 256, 256);
    k_alpha_node<8><<<aggGrid, 256>>>(as1, ad1);
    k_aggregate<8><<<aggGrid, 256>>>(ea, b1);

    // layer 2: 256 -> 32, heads=1  (SIMT)
    k_prep<<<1, 32>>>(we2, ae2, 1);
    k_gemm<<<dim3(1, (NN + 127) / 128), 256>>>(w2, NN, 256, 32);
    k_alpha_node<1><<<aggGrid, 256>>>(as2, ad2);
    k_aggregate<1><<<aggGrid, 256>>>(ea, b2);

    // final edge MLP (factorized)
    k_mlp_pre<<<(NN * 64 + 255) / 256, 256>>>(mw1);
    k_mlp<<<(NE + 127) / 128, 128>>>(ei, mb1, mw2, mb2, out);
}